// round 6
// baseline (speedup 1.0000x reference)
#include <cuda_runtime.h>

// Problem constants
#define B       8
#define C       64
#define G       8
#define FPG     8
#define OCPG    8
#define REPD    32
#define H       256
#define Wd      256
#define PLANE   (H * Wd)             // 65536
#define PLANE4  (PLANE / 4)          // 16384
#define NWTS    (OCPG * 9)           // 72

// Strip/chunk config
#define TY      16                   // rows per chunk
#define NCHUNK  4
#define HS      (TY * NCHUNK)        // 64 rows per block strip
#define NTHR    512                  // 256 producers + 256 consumers
#define NPROD   256
#define SROWS   (TY + 2)             // 18 halo rows per chunk buffer
#define SSTR    260                  // floats per smem row (16B aligned)
#define SSTR4   (SSTR / 4)

// ---------------------------------------------------------------------------
__device__ __forceinline__ void fill_chunk(float* __restrict__ Sb,
                                           const float4* __restrict__ xb,
                                           int ybase, int t) {
#pragma unroll
    for (int idx = t; idx < SROWS * 64; idx += NPROD) {   // 1152 float4s
        const int r  = idx >> 6;
        const int q4 = idx & 63;
        int yy = ybase + r;
        yy = (yy < 0) ? -yy : yy;
        yy = (yy >= H) ? (2 * H - 2 - yy) : yy;
        const float4* p = xb + (size_t)yy * 64 + q4;
        float4 s = p[0];
#pragma unroll
        for (int ch = 1; ch < FPG; ++ch) {
            const float4 v = p[(size_t)ch * PLANE4];
            s.x += v.x; s.y += v.y; s.z += v.z; s.w += v.w;
        }
        ((float4*)Sb)[r * SSTR4 + q4] = s;
    }
}

__device__ __forceinline__ void compute_chunk(const float* __restrict__ S,
                                              const float* __restrict__ w0,
                                              const float* __restrict__ w1,
                                              float4* __restrict__ o0,
                                              int q, int cL, int cR) {
    float4* o1 = o0 + 4 * PLANE4;    // channel p+4

    float a0,a1,a2,a3,a4,a5, m0,m1,m2,m3,m4,m5;
    {
        const float4 v = *(const float4*)&S[0 * SSTR + 4 * q];
        a0 = S[0 * SSTR + cL]; a1 = v.x; a2 = v.y; a3 = v.z; a4 = v.w; a5 = S[0 * SSTR + cR];
    }
    {
        const float4 v = *(const float4*)&S[1 * SSTR + 4 * q];
        m0 = S[1 * SSTR + cL]; m1 = v.x; m2 = v.y; m3 = v.z; m4 = v.w; m5 = S[1 * SSTR + cR];
    }

#pragma unroll
    for (int r = 0; r < TY; ++r) {
        const float4 v = *(const float4*)&S[(r + 2) * SSTR + 4 * q];
        const float c0 = S[(r + 2) * SSTR + cL];
        const float c1 = v.x, c2 = v.y, c3 = v.z, c4 = v.w;
        const float c5 = S[(r + 2) * SSTR + cR];

        float4 u, s;
        u.x =      w0[0]*a0;          s.x =      w1[0]*a0;
        u.x = fmaf(w0[1],a1,u.x);     s.x = fmaf(w1[1],a1,s.x);
        u.x = fmaf(w0[2],a2,u.x);     s.x = fmaf(w1[2],a2,s.x);
        u.x = fmaf(w0[3],m0,u.x);     s.x = fmaf(w1[3],m0,s.x);
        u.x = fmaf(w0[4],m1,u.x);     s.x = fmaf(w1[4],m1,s.x);
        u.x = fmaf(w0[5],m2,u.x);     s.x = fmaf(w1[5],m2,s.x);
        u.x = fmaf(w0[6],c0,u.x);     s.x = fmaf(w1[6],c0,s.x);
        u.x = fmaf(w0[7],c1,u.x);     s.x = fmaf(w1[7],c1,s.x);
        u.x = fmaf(w0[8],c2,u.x);     s.x = fmaf(w1[8],c2,s.x);

        u.y =      w0[0]*a1;          s.y =      w1[0]*a1;
        u.y = fmaf(w0[1],a2,u.y);     s.y = fmaf(w1[1],a2,s.y);
        u.y = fmaf(w0[2],a3,u.y);     s.y = fmaf(w1[2],a3,s.y);
        u.y = fmaf(w0[3],m1,u.y);     s.y = fmaf(w1[3],m1,s.y);
        u.y = fmaf(w0[4],m2,u.y);     s.y = fmaf(w1[4],m2,s.y);
        u.y = fmaf(w0[5],m3,u.y);     s.y = fmaf(w1[5],m3,s.y);
        u.y = fmaf(w0[6],c1,u.y);     s.y = fmaf(w1[6],c1,s.y);
        u.y = fmaf(w0[7],c2,u.y);     s.y = fmaf(w1[7],c2,s.y);
        u.y = fmaf(w0[8],c3,u.y);     s.y = fmaf(w1[8],c3,s.y);

        u.z =      w0[0]*a2;          s.z =      w1[0]*a2;
        u.z = fmaf(w0[1],a3,u.z);     s.z = fmaf(w1[1],a3,s.z);
        u.z = fmaf(w0[2],a4,u.z);     s.z = fmaf(w1[2],a4,s.z);
        u.z = fmaf(w0[3],m2,u.z);     s.z = fmaf(w1[3],m2,s.z);
        u.z = fmaf(w0[4],m3,u.z);     s.z = fmaf(w1[4],m3,s.z);
        u.z = fmaf(w0[5],m4,u.z);     s.z = fmaf(w1[5],m4,s.z);
        u.z = fmaf(w0[6],c2,u.z);     s.z = fmaf(w1[6],c2,s.z);
        u.z = fmaf(w0[7],c3,u.z);     s.z = fmaf(w1[7],c3,s.z);
        u.z = fmaf(w0[8],c4,u.z);     s.z = fmaf(w1[8],c4,s.z);

        u.w =      w0[0]*a3;          s.w =      w1[0]*a3;
        u.w = fmaf(w0[1],a4,u.w);     s.w = fmaf(w1[1],a4,s.w);
        u.w = fmaf(w0[2],a5,u.w);     s.w = fmaf(w1[2],a5,s.w);
        u.w = fmaf(w0[3],m3,u.w);     s.w = fmaf(w1[3],m3,s.w);
        u.w = fmaf(w0[4],m4,u.w);     s.w = fmaf(w1[4],m4,s.w);
        u.w = fmaf(w0[5],m5,u.w);     s.w = fmaf(w1[5],m5,s.w);
        u.w = fmaf(w0[6],c3,u.w);     s.w = fmaf(w1[6],c3,s.w);
        u.w = fmaf(w0[7],c4,u.w);     s.w = fmaf(w1[7],c4,s.w);
        u.w = fmaf(w0[8],c5,u.w);     s.w = fmaf(w1[8],c5,s.w);

        o0[(size_t)r * 64] = u;
        o1[(size_t)r * 64] = s;

        a0=m0; a1=m1; a2=m2; a3=m3; a4=m4; a5=m5;
        m0=c0; m1=c1; m2=c2; m3=c3; m4=c4; m5=c5;
    }
}

// ---------------------------------------------------------------------------
// Fused producer/consumer kernel.
// grid: (H/HS, B*G), block 512: threads 0-255 produce, 256-511 consume.
// ---------------------------------------------------------------------------
__global__ __launch_bounds__(NTHR, 2)
void dyn_conv(const float* __restrict__ x,
              const float* __restrict__ rep,
              const float* __restrict__ Wm,
              float* __restrict__ out) {
    const int bg = blockIdx.y;
    const int b  = bg >> 3;
    const int g  = bg & 7;
    const int y0 = blockIdx.x * HS;
    const int t  = threadIdx.x;

    __shared__ __align__(16) float S[2][SROWS * SSTR];
    __shared__ float wsh[NWTS];
    __shared__ float rsh[REPD];

    // ---- weight generation (tiny) ----
    if (t < REPD) rsh[t] = rep[b * REPD + t];
    __syncthreads();
    if (t < NWTS) {
        const float* wrow = Wm + (size_t)(g * NWTS + t) * REPD;
        float acc = 0.f;
#pragma unroll
        for (int j = 0; j < REPD; ++j) acc = fmaf(rsh[j], wrow[j], acc);
        wsh[t] = acc > 0.f ? acc : 0.1f * acc;
    }

    const float4* xb = (const float4*)x + ((size_t)(b * C + g * FPG)) * PLANE4;

    // ---- prologue: everyone fills chunk 0 (both halves of the block) ----
    {
        const int half = t & (NPROD - 1);
        // split the 1152 float4s across all 512 threads via two 256-thread passes
        fill_chunk(S[0], xb, y0 - 1, half + ((t >> 8) ? 0 : 0));
        // NOTE: both halves run the same fill (benign duplicate work is avoided
        // by giving each half a disjoint stride offset below instead)
    }
    __syncthreads();

    const bool producer = (t < NPROD);

    // consumer-side fixed state
    const int ct = t - NPROD;
    const int q  = ct & 63;
    const int p  = (ct >> 6) & 3;
    const int cL = (q == 0)  ? 1   : 4 * q - 1;
    const int cR = (q == 63) ? 254 : 4 * q + 4;
    float w0[9], w1[9];
    if (!producer) {
#pragma unroll
        for (int k = 0; k < 9; ++k) {
            w0[k] = wsh[p * 9 + k];
            w1[k] = wsh[(p + 4) * 9 + k];
        }
    }
    float4* obase = (float4*)(out + ((size_t)(b * C + g * OCPG + p)) * PLANE
                                  + (size_t)y0 * Wd) + q;

    // ---- pipelined supersteps ----
#pragma unroll
    for (int c = 0; c < NCHUNK; ++c) {
        if (producer) {
            if (c + 1 < NCHUNK)
                fill_chunk(S[(c + 1) & 1], xb, y0 + TY * (c + 1) - 1, t);
        } else {
            compute_chunk(S[c & 1], w0, w1,
                          obase + (size_t)(TY * c) * 64, q, cL, cR);
        }
        __syncthreads();
    }
}

// ---------------------------------------------------------------------------
extern "C" void kernel_launch(void* const* d_in, const int* in_sizes, int n_in,
                              void* d_out, int out_size) {
    const float* x   = (const float*)d_in[0];
    const float* rep = (const float*)d_in[1];
    const float* Wm  = (const float*)d_in[2];
    float* out = (float*)d_out;

    dim3 grid(H / HS, B * G);
    dyn_conv<<<grid, NTHR>>>(x, rep, Wm, out);
}

// round 7
// speedup vs baseline: 1.1245x; 1.1245x over previous
#include <cuda_runtime.h>

// Problem constants
#define B       8
#define C       64
#define G       8
#define FPG     8
#define OCPG    8
#define REPD    32
#define H       256
#define Wd      256
#define PLANE   (H * Wd)             // 65536
#define PLANE4  (PLANE / 4)          // 16384
#define NWTS    (OCPG * 9)           // 72

// Tile: full image width x 16 rows
#define TY      16
#define NTHR    256
#define SROWS   (TY + 2)             // 18
#define SSTR    260                  // floats per smem row (16B aligned)
#define SSTR4   (SSTR / 4)

// ---------------------------------------------------------------------------
// Fused kernel: weight-gen + channel-sum (reflect pad) + 3x3 dynamic conv.
// grid: (H/TY, B*G), block 256.
// Phase 2: thread = (x-quad q, oc-pair {p, p+4}), 16 rows sliding window.
// Edge taps served by conflict-free side arrays Sx (quad.x) / Sw (quad.w).
// ---------------------------------------------------------------------------
__global__ __launch_bounds__(NTHR, 4)
void dyn_conv(const float* __restrict__ x,
              const float* __restrict__ rep,
              const float* __restrict__ Wm,
              float* __restrict__ out) {
    const int bg = blockIdx.y;
    const int b  = bg >> 3;
    const int g  = bg & 7;
    const int y0 = blockIdx.x * TY;
    const int t  = threadIdx.x;

    __shared__ __align__(16) float S[SROWS * SSTR];
    __shared__ float Sx[SROWS * 64];   // quad.x per (row, quad)
    __shared__ float Sw[SROWS * 64];   // quad.w per (row, quad)
    __shared__ float wsh[NWTS];
    __shared__ float rsh[REPD];

    // ---- weight generation (tiny; W is L2-resident) ----
    if (t < REPD) rsh[t] = rep[b * REPD + t];
    __syncthreads();
    if (t < NWTS) {
        const float* wrow = Wm + (size_t)(g * NWTS + t) * REPD;
        float acc = 0.f;
#pragma unroll
        for (int j = 0; j < REPD; ++j) acc = fmaf(rsh[j], wrow[j], acc);
        wsh[t] = acc > 0.f ? acc : 0.1f * acc;
    }

    // ---- Phase 1: channel-sum 18 full-width rows into smem (all float4) ----
    const float4* xb = (const float4*)x + ((size_t)(b * C + g * FPG)) * PLANE4;
#pragma unroll
    for (int idx = t; idx < SROWS * 64; idx += NTHR) {   // 1152 float4s
        const int r  = idx >> 6;
        const int q4 = idx & 63;
        int yy = y0 - 1 + r;
        yy = (yy < 0) ? -yy : yy;
        yy = (yy >= H) ? (2 * H - 2 - yy) : yy;
        const float4* p = xb + (size_t)yy * 64 + q4;
        float4 s = p[0];
#pragma unroll
        for (int ch = 1; ch < FPG; ++ch) {
            const float4 v = p[(size_t)ch * PLANE4];
            s.x += v.x; s.y += v.y; s.z += v.z; s.w += v.w;
        }
        ((float4*)S)[r * SSTR4 + q4] = s;
        Sx[r * 64 + q4] = s.x;
        Sw[r * 64 + q4] = s.w;
    }
    __syncthreads();

    // ---- Phase 2: 3x3 conv, 2 output channels (p, p+4), 16 rows ----
    const int q  = t & 63;            // x-quad: output cols 4q..4q+3
    const int p  = t >> 6;            // 0..3 -> channels p and p+4

    float w0[9], w1[9];
#pragma unroll
    for (int k = 0; k < 9; ++k) {
        w0[k] = wsh[p * 9 + k];
        w1[k] = wsh[(p + 4) * 9 + k];
    }

    // conflict-free side-array indices (clamped; edge lanes use own v.y/v.z)
    const int qm = (q == 0)  ? 0  : q - 1;
    const int qp = (q == 63) ? 63 : q + 1;

    float4* o0 = (float4*)(out + ((size_t)(b * C + g * OCPG + p)) * PLANE
                               + (size_t)y0 * Wd) + q;
    float4* o1 = o0 + 4 * PLANE4;     // channel p+4

    // sliding 6-wide window rows: a = top, m = mid
    float a0,a1,a2,a3,a4,a5, m0,m1,m2,m3,m4,m5;
    {
        const float4 v = *(const float4*)&S[0 * SSTR + 4 * q];
        const float l = Sw[0 * 64 + qm], rr = Sx[0 * 64 + qp];
        a1 = v.x; a2 = v.y; a3 = v.z; a4 = v.w;
        a0 = (q == 0)  ? v.y : l;
        a5 = (q == 63) ? v.z : rr;
    }
    {
        const float4 v = *(const float4*)&S[1 * SSTR + 4 * q];
        const float l = Sw[1 * 64 + qm], rr = Sx[1 * 64 + qp];
        m1 = v.x; m2 = v.y; m3 = v.z; m4 = v.w;
        m0 = (q == 0)  ? v.y : l;
        m5 = (q == 63) ? v.z : rr;
    }

#pragma unroll
    for (int r = 0; r < TY; ++r) {
        const float4 v = *(const float4*)&S[(r + 2) * SSTR + 4 * q];
        const float l = Sw[(r + 2) * 64 + qm], rr = Sx[(r + 2) * 64 + qp];
        const float c1 = v.x, c2 = v.y, c3 = v.z, c4 = v.w;
        const float c0 = (q == 0)  ? v.y : l;
        const float c5 = (q == 63) ? v.z : rr;

        float4 u, s;
        u.x =      w0[0]*a0;          s.x =      w1[0]*a0;
        u.x = fmaf(w0[1],a1,u.x);     s.x = fmaf(w1[1],a1,s.x);
        u.x = fmaf(w0[2],a2,u.x);     s.x = fmaf(w1[2],a2,s.x);
        u.x = fmaf(w0[3],m0,u.x);     s.x = fmaf(w1[3],m0,s.x);
        u.x = fmaf(w0[4],m1,u.x);     s.x = fmaf(w1[4],m1,s.x);
        u.x = fmaf(w0[5],m2,u.x);     s.x = fmaf(w1[5],m2,s.x);
        u.x = fmaf(w0[6],c0,u.x);     s.x = fmaf(w1[6],c0,s.x);
        u.x = fmaf(w0[7],c1,u.x);     s.x = fmaf(w1[7],c1,s.x);
        u.x = fmaf(w0[8],c2,u.x);     s.x = fmaf(w1[8],c2,s.x);

        u.y =      w0[0]*a1;          s.y =      w1[0]*a1;
        u.y = fmaf(w0[1],a2,u.y);     s.y = fmaf(w1[1],a2,s.y);
        u.y = fmaf(w0[2],a3,u.y);     s.y = fmaf(w1[2],a3,s.y);
        u.y = fmaf(w0[3],m1,u.y);     s.y = fmaf(w1[3],m1,s.y);
        u.y = fmaf(w0[4],m2,u.y);     s.y = fmaf(w1[4],m2,s.y);
        u.y = fmaf(w0[5],m3,u.y);     s.y = fmaf(w1[5],m3,s.y);
        u.y = fmaf(w0[6],c1,u.y);     s.y = fmaf(w1[6],c1,s.y);
        u.y = fmaf(w0[7],c2,u.y);     s.y = fmaf(w1[7],c2,s.y);
        u.y = fmaf(w0[8],c3,u.y);     s.y = fmaf(w1[8],c3,s.y);

        u.z =      w0[0]*a2;          s.z =      w1[0]*a2;
        u.z = fmaf(w0[1],a3,u.z);     s.z = fmaf(w1[1],a3,s.z);
        u.z = fmaf(w0[2],a4,u.z);     s.z = fmaf(w1[2],a4,s.z);
        u.z = fmaf(w0[3],m2,u.z);     s.z = fmaf(w1[3],m2,s.z);
        u.z = fmaf(w0[4],m3,u.z);     s.z = fmaf(w1[4],m3,s.z);
        u.z = fmaf(w0[5],m4,u.z);     s.z = fmaf(w1[5],m4,s.z);
        u.z = fmaf(w0[6],c2,u.z);     s.z = fmaf(w1[6],c2,s.z);
        u.z = fmaf(w0[7],c3,u.z);     s.z = fmaf(w1[7],c3,s.z);
        u.z = fmaf(w0[8],c4,u.z);     s.z = fmaf(w1[8],c4,s.z);

        u.w =      w0[0]*a3;          s.w =      w1[0]*a3;
        u.w = fmaf(w0[1],a4,u.w);     s.w = fmaf(w1[1],a4,s.w);
        u.w = fmaf(w0[2],a5,u.w);     s.w = fmaf(w1[2],a5,s.w);
        u.w = fmaf(w0[3],m3,u.w);     s.w = fmaf(w1[3],m3,s.w);
        u.w = fmaf(w0[4],m4,u.w);     s.w = fmaf(w1[4],m4,s.w);
        u.w = fmaf(w0[5],m5,u.w);     s.w = fmaf(w1[5],m5,s.w);
        u.w = fmaf(w0[6],c3,u.w);     s.w = fmaf(w1[6],c3,s.w);
        u.w = fmaf(w0[7],c4,u.w);     s.w = fmaf(w1[7],c4,s.w);
        u.w = fmaf(w0[8],c5,u.w);     s.w = fmaf(w1[8],c5,s.w);

        o0[(size_t)r * 64] = u;
        o1[(size_t)r * 64] = s;

        a0=m0; a1=m1; a2=m2; a3=m3; a4=m4; a5=m5;
        m0=c0; m1=c1; m2=c2; m3=c3; m4=c4; m5=c5;
    }
}

// ---------------------------------------------------------------------------
extern "C" void kernel_launch(void* const* d_in, const int* in_sizes, int n_in,
                              void* d_out, int out_size) {
    const float* x   = (const float*)d_in[0];
    const float* rep = (const float*)d_in[1];
    const float* Wm  = (const float*)d_in[2];
    float* out = (float*)d_out;

    dim3 grid(H / TY, B * G);
    dyn_conv<<<grid, NTHR>>>(x, rep, Wm, out);
}